// round 13
// baseline (speedup 1.0000x reference)
#include <cuda_runtime.h>
#include <cuda_fp16.h>
#include <math.h>
#include <stdint.h>

#define NB 4096
#define NF 256
#define NP 5000
#define NCHUNK 4
#define CHUNK_P 1280
#define NMTILE 32
#define NCTA (NMTILE * NCHUNK)        // 128
#define CAPC 16
#define IGNORE_INDEX 5554
#define AST 264                       // A smem row stride (halfs), 528B
#define BST 72                        // B smem row stride (halfs), 144B
#define A_BYTES (128 * AST * 2)       // 67584
#define B_STAGE (256 * BST * 2)       // 36864
#define NSTAGE 3
#define SM_META (A_BYTES + NSTAGE * B_STAGE)       // 178176
#define SM_RED  (SM_META + 4 * 128 * 4)            // 180224
#define SM_RLAB (SM_RED + 8 * 128 * 4)             // 184320
#define SMEM_TOTAL (SM_RLAB + CHUNK_P * 4)         // 189440
#define NI 40                         // 10 nt-tiles * 4 k-chunks

// ---------------- static scratch ----------------
__device__ __align__(16) __half g_inh[NB * NF];
__device__ __align__(16) __half g_lih[NP * NF];
__device__ __align__(16) __half g_rlh[NP * NF];
__device__ float g_s_inst[NB * NCHUNK];
__device__ float g_s_reid[NB * NCHUNK];
__device__ int   g_pcnt[NB * NCHUNK];
__device__ float g_posx[NB * NCHUNK * CAPC];
__device__ float g_xt[NB];
__device__ float g_fc[NCTA];
__device__ int   g_ticket;

// ---------------- helpers ----------------
__device__ __forceinline__ uint32_t smem_u32(const void* p) {
    uint32_t a;
    asm("{ .reg .u64 t; cvta.to.shared.u64 t, %1; cvt.u32.u64 %0, t; }"
        : "=r"(a) : "l"(p));
    return a;
}
__device__ __forceinline__ void cp16(uint32_t dst, const void* src, int sz) {
    asm volatile("cp.async.cg.shared.global [%0], [%1], 16, %2;"
                 :: "r"(dst), "l"(src), "r"(sz) : "memory");
}
#define CP_COMMIT() asm volatile("cp.async.commit_group;" ::: "memory")
#define CP_WAIT2()  asm volatile("cp.async.wait_group 2;" ::: "memory")

__device__ __forceinline__ void ldmx4(uint32_t* r, uint32_t addr) {
    asm volatile("ldmatrix.sync.aligned.m8n8.x4.shared.b16 {%0,%1,%2,%3}, [%4];"
                 : "=r"(r[0]), "=r"(r[1]), "=r"(r[2]), "=r"(r[3]) : "r"(addr));
}
__device__ __forceinline__ void mma16(float* c, const uint32_t* a,
                                      uint32_t b0, uint32_t b1) {
    asm("mma.sync.aligned.m16n8k16.row.col.f32.f16.f16.f32 "
        "{%0,%1,%2,%3}, {%4,%5,%6,%7}, {%8,%9}, {%0,%1,%2,%3};"
        : "+f"(c[0]), "+f"(c[1]), "+f"(c[2]), "+f"(c[3])
        : "r"(a[0]), "r"(a[1]), "r"(a[2]), "r"(a[3]), "r"(b0), "r"(b1));
}

__device__ __forceinline__ uint2 cvt2(float4 v) {
    uint2 o;
    half2 lo = __floats2half2_rn(v.x, v.y);
    half2 hi = __floats2half2_rn(v.z, v.w);
    o.x = *(uint32_t*)&lo;
    o.y = *(uint32_t*)&hi;
    return o;
}

// ---------------------------------------------------------------------------
// K0: flat grid-stride f32->f16 convert + ticket reset + fc partials.
// ---------------------------------------------------------------------------
#define T0 (NB * NF / 4)
#define T1 (NP * NF / 4)
#define TTOT (T0 + 2 * T1)
#define CONV_GRID 1184

__global__ void __launch_bounds__(256)
convert_kernel(const float* __restrict__ inp, const float* __restrict__ li,
               const float* __restrict__ rl, const int* __restrict__ roi_label)
{
    __shared__ float sred[8];
    int tid = threadIdx.x, wid = tid >> 5, lane = tid & 31;
    int idx = blockIdx.x * blockDim.x + tid;
    int stride = blockDim.x * gridDim.x;
    if (blockIdx.x == 0 && tid == 0) g_ticket = 0;

#pragma unroll 4
    for (int i = idx; i < TTOT; i += stride) {
        const float4* src;
        uint2* dst;
        int j;
        if (i < T0)           { src = (const float4*)inp; dst = (uint2*)g_inh; j = i; }
        else if (i < T0 + T1) { src = (const float4*)li;  dst = (uint2*)g_lih; j = i - T0; }
        else                  { src = (const float4*)rl;  dst = (uint2*)g_rlh; j = i - T0 - T1; }
        dst[j] = cvt2(src[j]);
    }

    if (blockIdx.x < NCTA) {
        int m0 = blockIdx.x * (NB / NCTA);
        float acc = 0.0f;
        for (int r = wid; r < NB / NCTA; r += 8) {
            int m = m0 + r;
            int t = roi_label[m] - 1;
            if (t >= 0) {
                const float4* a = (const float4*)(inp + (size_t)m * NF);
                const float4* b = (const float4*)(li + (size_t)t * NF);
                float s = 0.0f;
#pragma unroll
                for (int i = 0; i < 2; i++) {
                    float4 av = a[lane + 32 * i], bv = b[lane + 32 * i];
                    float dx = bv.x - av.x, dy = bv.y - av.y;
                    float dz = bv.z - av.z, dw = bv.w - av.w;
                    s += dx * dx + dy * dy + dz * dz + dw * dw;
                }
#pragma unroll
                for (int o = 16; o; o >>= 1) s += __shfl_xor_sync(0xffffffffu, s, o);
                acc += s;
            }
        }
        if (lane == 0) sred[wid] = acc;
        __syncthreads();
        if (tid == 0) {
            float s = 0.0f;
            for (int w = 0; w < 8; w++) s += sred[w];
            g_fc[blockIdx.x] = s;
        }
    }
}

// ---------------------------------------------------------------------------
// Finalize (runs on the last CTA of main_kernel; 512 threads)
// ---------------------------------------------------------------------------
__device__ __noinline__ void do_finalize(const int* __restrict__ roi_label,
                                         const int* __restrict__ reid_labels,
                                         float* __restrict__ out,
                                         float* __restrict__ sred)
{
    int tid = threadIdx.x, wid = tid >> 5, lane = tid & 31;
    float instS = 0.f, ceS = 0.f, n1 = 0.f, n2 = 0.f, n3 = 0.f;
    float fcS = (tid < NCTA) ? g_fc[tid] : 0.f;

    for (int m = tid; m < NB; m += 512) {
        int t = roi_label[m] - 1;
        bool v = (t >= 0);
        int label = v ? t : 0;
        int lreid = reid_labels[label];
        bool v2 = v && (lreid >= 0);
        int lr = lreid > 0 ? lreid : 0;
        bool v3 = v2 && (lr != IGNORE_INDEX);
        n1 += v ? 1.f : 0.f;
        n2 += v2 ? 1.f : 0.f;
        n3 += v3 ? 1.f : 0.f;
        if (v2) {
            float s = 0.f;
#pragma unroll
            for (int c = 0; c < NCHUNK; c++) s += g_s_inst[m * NCHUNK + c];
            float lse = (s > 0.f) ? (30.f + logf(s)) : -1e30f;
            int cnt = 0;
            float sum = 0.f;
#pragma unroll
            for (int c = 0; c < NCHUNK; c++) {
                int pc = g_pcnt[m * NCHUNK + c];
                cnt += pc;
                int pl = pc < CAPC ? pc : CAPC;
                for (int q = 0; q < pl; q++)
                    sum += log1pf(expf(lse - g_posx[(m * NCHUNK + c) * CAPC + q]));
            }
            instS += sum / fmaxf((float)cnt, 1.f);
            if (v3) {
                float s2 = 0.f;
#pragma unroll
                for (int c = 0; c < NCHUNK; c++) s2 += g_s_reid[m * NCHUNK + c];
                ceS += (30.f + logf(s2)) - g_xt[m];
            }
        }
    }
    float vals[6] = {instS, ceS, n1, n2, n3, fcS};
#pragma unroll
    for (int k = 0; k < 6; k++)
#pragma unroll
        for (int o = 16; o; o >>= 1)
            vals[k] += __shfl_xor_sync(0xffffffffu, vals[k], o);
    if (lane == 0)
        for (int k = 0; k < 6; k++) sred[wid * 6 + k] = vals[k];
    __syncthreads();
    if (tid == 0) {
        float tot[6] = {0, 0, 0, 0, 0, 0};
        for (int w = 0; w < 16; w++)
            for (int k = 0; k < 6; k++) tot[k] += sred[w * 6 + k];
        out[0] = tot[5] / (fmaxf(tot[2], 1.f) * (float)NF)
               + tot[1] / fmaxf(tot[4], 1.f)
               + tot[0] / fmaxf(tot[3], 1.f);
    }
}

// ---------------------------------------------------------------------------
// Main fused kernel: grid (32 m-tiles, 4 p-chunks) = 128 CTAs, 512 threads.
// R9 pipeline: 3-stage cp.async, wait_group 2, two syncs per iteration.
// Last CTA (ticket) runs the finalize reduction.
// ---------------------------------------------------------------------------
__global__ void __launch_bounds__(512, 1)
main_kernel(const int* __restrict__ roi_label, const int* __restrict__ reid_labels,
            float* __restrict__ out)
{
    extern __shared__ char smem[];
    char* sB = smem + A_BYTES;
    int*   s_lreid = (int*)(smem + SM_META);
    int*   s_lr    = s_lreid + 128;
    int*   s_v2    = s_lr + 128;
    int*   s_pcnt  = s_v2 + 128;
    float* s_red2  = (float*)(smem + SM_RED);    // [8][128]
    int*   s_rlab  = (int*)(smem + SM_RLAB);     // [CHUNK_P]
    __shared__ int s_last;

    const uint32_t sA_a = smem_u32(smem);
    const uint32_t sB_a = smem_u32(sB);

    int tid = threadIdx.x;
    int wid = tid >> 5, lane = tid & 31;
    int qid = lane >> 2, tg = lane & 3;
    int mw = wid >> 3, nw = wid & 7;
    int m0 = blockIdx.x * 128;
    int chunk = blockIdx.y;
    int pbase = chunk * CHUNK_P;

    if (tid < 128) {
        int m = m0 + tid;
        int t = roi_label[m] - 1;
        bool v = (t >= 0);
        int label = v ? t : 0;
        int lreid = reid_labels[label];
        s_lreid[tid] = lreid;
        s_lr[tid] = lreid > 0 ? lreid : 0;
        s_v2[tid] = (v && lreid >= 0) ? 1 : 0;
        s_pcnt[tid] = 0;
    }
    for (int j = tid; j < CHUNK_P; j += 512) {
        int p = pbase + j;
        s_rlab[j] = (p < NP) ? reid_labels[p] : (int)0x80000000;
    }

    // ---- stage A (f16, full 128x256) ----
    {
        const __half* Ain = g_inh + (size_t)m0 * NF;
#pragma unroll
        for (int j = 0; j < 8; j++) {
            int ci = tid + j * 512;
            int row = ci >> 5, c = ci & 31;
            cp16(sA_a + (uint32_t)(row * AST + c * 8) * 2, Ain + row * NF + c * 8, 16);
        }
    }
    auto issue_B = [&](int i, int buf) {
        int nt = i >> 2, kc = i & 3;
        const __half* lut = (nt < 5) ? g_lih : g_rlh;
        int p0 = pbase + (nt % 5) * 256;
        uint32_t dstBase = sB_a + (uint32_t)buf * B_STAGE;
#pragma unroll
        for (int j = 0; j < 4; j++) {
            int ci = tid + j * 512;
            int row = ci >> 3, c = ci & 7;
            int p = p0 + row;
            int pc = p < NP ? p : NP - 1;
            cp16(dstBase + (uint32_t)(row * BST + c * 8) * 2,
                 lut + (size_t)pc * NF + kc * 64 + c * 8, (p < NP) ? 16 : 0);
        }
    };
    issue_B(0, 0);
    CP_COMMIT();
    issue_B(1, 1);
    CP_COMMIT();
    issue_B(2, 2);
    CP_COMMIT();

    // ldmatrix lane bases
    uint32_t abase[4];
#pragma unroll
    for (int mf = 0; mf < 4; mf++)
        abase[mf] = sA_a + (uint32_t)((mw * 64 + mf * 16 + (lane & 15)) * AST
                                      + (lane >> 4) * 8) * 2;
    int noff = (lane & 7) + ((lane >> 4) << 3);
    uint32_t bbase = sB_a + (uint32_t)((nw * 32 + noff) * BST + ((lane & 8) ? 8 : 0)) * 2;

    float acc[4][4][4];
    float sacc[8];
#pragma unroll
    for (int q = 0; q < 8; q++) sacc[q] = 0.0f;

    int bufi = 0;
#pragma unroll 1
    for (int i = 0; i < NI; i++) {
        int nt = i >> 2, kc = i & 3;
        if (kc == 0) {
#pragma unroll
            for (int mf = 0; mf < 4; mf++)
#pragma unroll
                for (int nf = 0; nf < 4; nf++)
#pragma unroll
                    for (int r = 0; r < 4; r++) acc[mf][nf][r] = 0.0f;
        }
        CP_WAIT2();
        __syncthreads();

        uint32_t bstage = bbase + (uint32_t)bufi * B_STAGE;
#pragma unroll
        for (int kk = 0; kk < 4; kk++) {
            uint32_t a[4][4], b[8];
            uint32_t akb = (uint32_t)(kc * 4 + kk) * 32;
#pragma unroll
            for (int mf = 0; mf < 4; mf++) ldmx4(a[mf], abase[mf] + akb);
            ldmx4(b,     bstage + kk * 32);
            ldmx4(b + 4, bstage + 16 * BST * 2 + kk * 32);
#pragma unroll
            for (int nf = 0; nf < 4; nf++)
#pragma unroll
                for (int mf = 0; mf < 4; mf++)
                    mma16(acc[mf][nf], a[mf], b[nf * 2], b[nf * 2 + 1]);
        }
        __syncthreads();
        if (i + NSTAGE < NI) issue_B(i + NSTAGE, bufi);
        CP_COMMIT();
        bufi = (bufi == NSTAGE - 1) ? 0 : bufi + 1;

        if (kc == 3) {
            // ---------------- epilogue for tile nt ----------------
            int j0 = (nt % 5) * 256;
            bool inst = (nt < 5);
#pragma unroll
            for (int nf = 0; nf < 4; nf++) {
                int jb = j0 + nw * 32 + nf * 8 + tg * 2;
                int pb = pbase + jb;
                bool ok0 = pb < NP, ok1 = (pb + 1) < NP;
                int rl0 = 0, rl1 = 0;
                if (inst) { rl0 = s_rlab[jb]; rl1 = s_rlab[jb + 1]; }
#pragma unroll
                for (int mf = 0; mf < 4; mf++) {
#pragma unroll
                    for (int h = 0; h < 2; h++) {
                        int lrow = mw * 64 + mf * 16 + h * 8 + qid;
                        int slot = mf * 2 + h;
                        float x0 = acc[mf][nf][h * 2 + 0] * 30.0f;
                        float x1 = acc[mf][nf][h * 2 + 1] * 30.0f;
                        if (inst) {
                            int lre = s_lreid[lrow];
                            if (ok0) {
                                if (rl0 == lre) {
                                    if (s_v2[lrow]) {
                                        int idx = atomicAdd(&s_pcnt[lrow], 1);
                                        if (idx < CAPC)
                                            g_posx[((m0 + lrow) * NCHUNK + chunk) * CAPC + idx] = x0;
                                    }
                                } else sacc[slot] += __expf(x0 - 30.0f);
                            }
                            if (ok1) {
                                if (rl1 == lre) {
                                    if (s_v2[lrow]) {
                                        int idx = atomicAdd(&s_pcnt[lrow], 1);
                                        if (idx < CAPC)
                                            g_posx[((m0 + lrow) * NCHUNK + chunk) * CAPC + idx] = x1;
                                    }
                                } else sacc[slot] += __expf(x1 - 30.0f);
                            }
                        } else {
                            if (ok0) {
                                sacc[slot] += __expf(x0 - 30.0f);
                                if (pb == s_lr[lrow]) g_xt[m0 + lrow] = x0;
                            }
                            if (ok1) {
                                sacc[slot] += __expf(x1 - 30.0f);
                                if (pb + 1 == s_lr[lrow]) g_xt[m0 + lrow] = x1;
                            }
                        }
                    }
                }
            }
            if (nt == 4 || nt == 9) {
                // cross-warp reduction -> one scalar per row
#pragma unroll
                for (int slot = 0; slot < 8; slot++) {
                    float vv = sacc[slot];
                    vv += __shfl_xor_sync(0xffffffffu, vv, 1);
                    vv += __shfl_xor_sync(0xffffffffu, vv, 2);
                    if (tg == 0) {
                        int mf = slot >> 1, h = slot & 1;
                        int lrow = mw * 64 + mf * 16 + h * 8 + qid;
                        s_red2[nw * 128 + lrow] = vv;
                    }
                    sacc[slot] = 0.0f;
                }
                __syncthreads();
                if (tid < 128) {
                    float t = 0.f;
#pragma unroll
                    for (int w = 0; w < 8; w++) t += s_red2[w * 128 + tid];
                    if (nt == 4) g_s_inst[(m0 + tid) * NCHUNK + chunk] = t;
                    else         g_s_reid[(m0 + tid) * NCHUNK + chunk] = t;
                }
            }
        }
    }

    __syncthreads();
    if (tid < 128)
        g_pcnt[(m0 + tid) * NCHUNK + chunk] = s_pcnt[tid];

    // ---- last-CTA finalize ----
    __threadfence();
    __syncthreads();
    if (tid == 0) {
        int o = atomicAdd(&g_ticket, 1);
        s_last = (o == NCTA - 1) ? 1 : 0;
    }
    __syncthreads();
    if (s_last)
        do_finalize(roi_label, reid_labels, out, s_red2);
}

// ---------------------------------------------------------------------------
extern "C" void kernel_launch(void* const* d_in, const int* in_sizes, int n_in,
                              void* d_out, int out_size) {
    const float* inputs      = (const float*)d_in[0];
    const int*   roi_label   = (const int*)d_in[1];
    const float* lut_inst    = (const float*)d_in[2];
    const float* reid_lut    = (const float*)d_in[3];
    const int*   reid_labels = (const int*)d_in[4];
    float* out = (float*)d_out;

    cudaFuncSetAttribute(main_kernel, cudaFuncAttributeMaxDynamicSharedMemorySize,
                         SMEM_TOTAL);

    convert_kernel<<<CONV_GRID, 256>>>(inputs, lut_inst, reid_lut, roi_label);
    main_kernel<<<dim3(NMTILE, NCHUNK), 512, SMEM_TOTAL>>>(roi_label, reid_labels, out);
}

// round 14
// speedup vs baseline: 1.2905x; 1.2905x over previous
#include <cuda_runtime.h>
#include <cuda_fp16.h>
#include <math.h>
#include <stdint.h>

#define NB 4096
#define NF 256
#define NP 5000
#define NCHUNK 4
#define CHUNK_P 1280
#define NMTILE 32
#define NCTA (NMTILE * NCHUNK)        // 128
#define CAPC 16
#define IGNORE_INDEX 5554
#define AST 264                       // A smem row stride (halfs), 528B
#define BST 72                        // B smem row stride (halfs), 144B
#define A_BYTES (128 * AST * 2)       // 67584
#define B_STAGE (256 * BST * 2)       // 36864
#define NSTAGE 3
#define SM_META (A_BYTES + NSTAGE * B_STAGE)       // 178176
#define SM_RED  (SM_META + 4 * 128 * 4)            // 180224
#define SM_RLAB (SM_RED + 8 * 128 * 4)             // 184320
#define SMEM_TOTAL (SM_RLAB + CHUNK_P * 4)         // 189440
#define NI 40                         // 10 nt-tiles * 4 k-chunks

// ---------------- static scratch ----------------
__device__ __align__(16) __half g_inh[NB * NF];
__device__ __align__(16) __half g_lih[NP * NF];
__device__ __align__(16) __half g_rlh[NP * NF];
__device__ float g_s_inst[NB * NCHUNK];
__device__ float g_s_reid[NB * NCHUNK];
__device__ int   g_pcnt[NB * NCHUNK];
__device__ float g_posx[NB * NCHUNK * CAPC];
__device__ float g_xt[NB];
__device__ float g_fc[NCTA];
__device__ float g_part[NMTILE][5];
__device__ int   g_ticket;

// ---------------- helpers ----------------
__device__ __forceinline__ uint32_t smem_u32(const void* p) {
    uint32_t a;
    asm("{ .reg .u64 t; cvta.to.shared.u64 t, %1; cvt.u32.u64 %0, t; }"
        : "=r"(a) : "l"(p));
    return a;
}
__device__ __forceinline__ void cp16(uint32_t dst, const void* src, int sz) {
    asm volatile("cp.async.cg.shared.global [%0], [%1], 16, %2;"
                 :: "r"(dst), "l"(src), "r"(sz) : "memory");
}
#define CP_COMMIT() asm volatile("cp.async.commit_group;" ::: "memory")
#define CP_WAIT2()  asm volatile("cp.async.wait_group 2;" ::: "memory")

__device__ __forceinline__ void ldmx4(uint32_t* r, uint32_t addr) {
    asm volatile("ldmatrix.sync.aligned.m8n8.x4.shared.b16 {%0,%1,%2,%3}, [%4];"
                 : "=r"(r[0]), "=r"(r[1]), "=r"(r[2]), "=r"(r[3]) : "r"(addr));
}
__device__ __forceinline__ void mma16(float* c, const uint32_t* a,
                                      uint32_t b0, uint32_t b1) {
    asm("mma.sync.aligned.m16n8k16.row.col.f32.f16.f16.f32 "
        "{%0,%1,%2,%3}, {%4,%5,%6,%7}, {%8,%9}, {%0,%1,%2,%3};"
        : "+f"(c[0]), "+f"(c[1]), "+f"(c[2]), "+f"(c[3])
        : "r"(a[0]), "r"(a[1]), "r"(a[2]), "r"(a[3]), "r"(b0), "r"(b1));
}

__device__ __forceinline__ uint2 cvt2(float4 v) {
    uint2 o;
    half2 lo = __floats2half2_rn(v.x, v.y);
    half2 hi = __floats2half2_rn(v.z, v.w);
    o.x = *(uint32_t*)&lo;
    o.y = *(uint32_t*)&hi;
    return o;
}

// ---------------------------------------------------------------------------
// K0: flat grid-stride f32->f16 convert + ticket reset + fc partials.
// ---------------------------------------------------------------------------
#define T0 (NB * NF / 4)
#define T1 (NP * NF / 4)
#define TTOT (T0 + 2 * T1)
#define CONV_GRID 1184

__global__ void __launch_bounds__(256)
convert_kernel(const float* __restrict__ inp, const float* __restrict__ li,
               const float* __restrict__ rl, const int* __restrict__ roi_label)
{
    __shared__ float sred[8];
    int tid = threadIdx.x, wid = tid >> 5, lane = tid & 31;
    int idx = blockIdx.x * blockDim.x + tid;
    int stride = blockDim.x * gridDim.x;
    if (blockIdx.x == 0 && tid == 0) g_ticket = 0;

#pragma unroll 4
    for (int i = idx; i < TTOT; i += stride) {
        const float4* src;
        uint2* dst;
        int j;
        if (i < T0)           { src = (const float4*)inp; dst = (uint2*)g_inh; j = i; }
        else if (i < T0 + T1) { src = (const float4*)li;  dst = (uint2*)g_lih; j = i - T0; }
        else                  { src = (const float4*)rl;  dst = (uint2*)g_rlh; j = i - T0 - T1; }
        dst[j] = cvt2(src[j]);
    }

    if (blockIdx.x < NCTA) {
        int m0 = blockIdx.x * (NB / NCTA);
        float acc = 0.0f;
        for (int r = wid; r < NB / NCTA; r += 8) {
            int m = m0 + r;
            int t = roi_label[m] - 1;
            if (t >= 0) {
                const float4* a = (const float4*)(inp + (size_t)m * NF);
                const float4* b = (const float4*)(li + (size_t)t * NF);
                float s = 0.0f;
#pragma unroll
                for (int i = 0; i < 2; i++) {
                    float4 av = a[lane + 32 * i], bv = b[lane + 32 * i];
                    float dx = bv.x - av.x, dy = bv.y - av.y;
                    float dz = bv.z - av.z, dw = bv.w - av.w;
                    s += dx * dx + dy * dy + dz * dz + dw * dw;
                }
#pragma unroll
                for (int o = 16; o; o >>= 1) s += __shfl_xor_sync(0xffffffffu, s, o);
                acc += s;
            }
        }
        if (lane == 0) sred[wid] = acc;
        __syncthreads();
        if (tid == 0) {
            float s = 0.0f;
            for (int w = 0; w < 8; w++) s += sred[w];
            g_fc[blockIdx.x] = s;
        }
    }
}

// ---------------------------------------------------------------------------
// Main fused kernel: grid (32 m-tiles, 4 p-chunks) = 128 CTAs, 512 threads.
// R9 pipeline: 3-stage cp.async, wait_group 2, two syncs per iteration.
// ---------------------------------------------------------------------------
__global__ void __launch_bounds__(512, 1)
main_kernel(const int* __restrict__ roi_label, const int* __restrict__ reid_labels)
{
    extern __shared__ char smem[];
    char* sB = smem + A_BYTES;
    int*   s_lreid = (int*)(smem + SM_META);
    int*   s_lr    = s_lreid + 128;
    int*   s_v2    = s_lr + 128;
    int*   s_pcnt  = s_v2 + 128;
    float* s_red2  = (float*)(smem + SM_RED);    // [8][128]
    int*   s_rlab  = (int*)(smem + SM_RLAB);     // [CHUNK_P]

    const uint32_t sA_a = smem_u32(smem);
    const uint32_t sB_a = smem_u32(sB);

    int tid = threadIdx.x;
    int wid = tid >> 5, lane = tid & 31;
    int qid = lane >> 2, tg = lane & 3;
    int mw = wid >> 3, nw = wid & 7;
    int m0 = blockIdx.x * 128;
    int chunk = blockIdx.y;
    int pbase = chunk * CHUNK_P;

    if (tid < 128) {
        int m = m0 + tid;
        int t = roi_label[m] - 1;
        bool v = (t >= 0);
        int label = v ? t : 0;
        int lreid = reid_labels[label];
        s_lreid[tid] = lreid;
        s_lr[tid] = lreid > 0 ? lreid : 0;
        s_v2[tid] = (v && lreid >= 0) ? 1 : 0;
        s_pcnt[tid] = 0;
    }
    for (int j = tid; j < CHUNK_P; j += 512) {
        int p = pbase + j;
        s_rlab[j] = (p < NP) ? reid_labels[p] : (int)0x80000000;
    }

    // ---- stage A (f16, full 128x256) ----
    {
        const __half* Ain = g_inh + (size_t)m0 * NF;
#pragma unroll
        for (int j = 0; j < 8; j++) {
            int ci = tid + j * 512;
            int row = ci >> 5, c = ci & 31;
            cp16(sA_a + (uint32_t)(row * AST + c * 8) * 2, Ain + row * NF + c * 8, 16);
        }
    }
    auto issue_B = [&](int i, int buf) {
        int nt = i >> 2, kc = i & 3;
        const __half* lut = (nt < 5) ? g_lih : g_rlh;
        int p0 = pbase + (nt % 5) * 256;
        uint32_t dstBase = sB_a + (uint32_t)buf * B_STAGE;
#pragma unroll
        for (int j = 0; j < 4; j++) {
            int ci = tid + j * 512;
            int row = ci >> 3, c = ci & 7;
            int p = p0 + row;
            int pc = p < NP ? p : NP - 1;
            cp16(dstBase + (uint32_t)(row * BST + c * 8) * 2,
                 lut + (size_t)pc * NF + kc * 64 + c * 8, (p < NP) ? 16 : 0);
        }
    };
    issue_B(0, 0);
    CP_COMMIT();
    issue_B(1, 1);
    CP_COMMIT();
    issue_B(2, 2);
    CP_COMMIT();

    // ldmatrix lane bases
    uint32_t abase[4];
#pragma unroll
    for (int mf = 0; mf < 4; mf++)
        abase[mf] = sA_a + (uint32_t)((mw * 64 + mf * 16 + (lane & 15)) * AST
                                      + (lane >> 4) * 8) * 2;
    int noff = (lane & 7) + ((lane >> 4) << 3);
    uint32_t bbase = sB_a + (uint32_t)((nw * 32 + noff) * BST + ((lane & 8) ? 8 : 0)) * 2;

    float acc[4][4][4];
    float sacc[8];
#pragma unroll
    for (int q = 0; q < 8; q++) sacc[q] = 0.0f;

    int bufi = 0;
#pragma unroll 1
    for (int i = 0; i < NI; i++) {
        int nt = i >> 2, kc = i & 3;
        if (kc == 0) {
#pragma unroll
            for (int mf = 0; mf < 4; mf++)
#pragma unroll
                for (int nf = 0; nf < 4; nf++)
#pragma unroll
                    for (int r = 0; r < 4; r++) acc[mf][nf][r] = 0.0f;
        }
        CP_WAIT2();
        __syncthreads();

        uint32_t bstage = bbase + (uint32_t)bufi * B_STAGE;
#pragma unroll
        for (int kk = 0; kk < 4; kk++) {
            uint32_t a[4][4], b[8];
            uint32_t akb = (uint32_t)(kc * 4 + kk) * 32;
#pragma unroll
            for (int mf = 0; mf < 4; mf++) ldmx4(a[mf], abase[mf] + akb);
            ldmx4(b,     bstage + kk * 32);
            ldmx4(b + 4, bstage + 16 * BST * 2 + kk * 32);
#pragma unroll
            for (int nf = 0; nf < 4; nf++)
#pragma unroll
                for (int mf = 0; mf < 4; mf++)
                    mma16(acc[mf][nf], a[mf], b[nf * 2], b[nf * 2 + 1]);
        }
        __syncthreads();
        if (i + NSTAGE < NI) issue_B(i + NSTAGE, bufi);
        CP_COMMIT();
        bufi = (bufi == NSTAGE - 1) ? 0 : bufi + 1;

        if (kc == 3) {
            // ---------------- epilogue for tile nt ----------------
            int j0 = (nt % 5) * 256;
            bool inst = (nt < 5);
#pragma unroll
            for (int nf = 0; nf < 4; nf++) {
                int jb = j0 + nw * 32 + nf * 8 + tg * 2;
                int pb = pbase + jb;
                bool ok0 = pb < NP, ok1 = (pb + 1) < NP;
                int rl0 = 0, rl1 = 0;
                if (inst) { rl0 = s_rlab[jb]; rl1 = s_rlab[jb + 1]; }
#pragma unroll
                for (int mf = 0; mf < 4; mf++) {
#pragma unroll
                    for (int h = 0; h < 2; h++) {
                        int lrow = mw * 64 + mf * 16 + h * 8 + qid;
                        int slot = mf * 2 + h;
                        float x0 = acc[mf][nf][h * 2 + 0] * 30.0f;
                        float x1 = acc[mf][nf][h * 2 + 1] * 30.0f;
                        if (inst) {
                            int lre = s_lreid[lrow];
                            if (ok0) {
                                if (rl0 == lre) {
                                    if (s_v2[lrow]) {
                                        int idx = atomicAdd(&s_pcnt[lrow], 1);
                                        if (idx < CAPC)
                                            g_posx[((m0 + lrow) * NCHUNK + chunk) * CAPC + idx] = x0;
                                    }
                                } else sacc[slot] += __expf(x0 - 30.0f);
                            }
                            if (ok1) {
                                if (rl1 == lre) {
                                    if (s_v2[lrow]) {
                                        int idx = atomicAdd(&s_pcnt[lrow], 1);
                                        if (idx < CAPC)
                                            g_posx[((m0 + lrow) * NCHUNK + chunk) * CAPC + idx] = x1;
                                    }
                                } else sacc[slot] += __expf(x1 - 30.0f);
                            }
                        } else {
                            if (ok0) {
                                sacc[slot] += __expf(x0 - 30.0f);
                                if (pb == s_lr[lrow]) g_xt[m0 + lrow] = x0;
                            }
                            if (ok1) {
                                sacc[slot] += __expf(x1 - 30.0f);
                                if (pb + 1 == s_lr[lrow]) g_xt[m0 + lrow] = x1;
                            }
                        }
                    }
                }
            }
            if (nt == 4 || nt == 9) {
                // cross-warp reduction -> one scalar per row
#pragma unroll
                for (int slot = 0; slot < 8; slot++) {
                    float vv = sacc[slot];
                    vv += __shfl_xor_sync(0xffffffffu, vv, 1);
                    vv += __shfl_xor_sync(0xffffffffu, vv, 2);
                    if (tg == 0) {
                        int mf = slot >> 1, h = slot & 1;
                        int lrow = mw * 64 + mf * 16 + h * 8 + qid;
                        s_red2[nw * 128 + lrow] = vv;
                    }
                    sacc[slot] = 0.0f;
                }
                __syncthreads();
                if (tid < 128) {
                    float t = 0.f;
#pragma unroll
                    for (int w = 0; w < 8; w++) t += s_red2[w * 128 + tid];
                    if (nt == 4) g_s_inst[(m0 + tid) * NCHUNK + chunk] = t;
                    else         g_s_reid[(m0 + tid) * NCHUNK + chunk] = t;
                }
            }
        }
    }

    __syncthreads();
    if (tid < 128)
        g_pcnt[(m0 + tid) * NCHUNK + chunk] = s_pcnt[tid];
}

// ---------------------------------------------------------------------------
// Finalize: 32 CTAs x 128 threads, one row per thread; last CTA sums all.
// ---------------------------------------------------------------------------
__global__ void __launch_bounds__(128)
finalize_kernel(const int* __restrict__ roi_label,
                const int* __restrict__ reid_labels, float* __restrict__ out)
{
    __shared__ float sred[4][5];
    __shared__ int s_last;
    int tid = threadIdx.x, wid = tid >> 5, lane = tid & 31;
    int m = blockIdx.x * 128 + tid;

    int t = roi_label[m] - 1;
    bool v = (t >= 0);
    int label = v ? t : 0;
    int lreid = reid_labels[label];
    bool v2 = v && (lreid >= 0);
    int lr = lreid > 0 ? lreid : 0;
    bool v3 = v2 && (lr != IGNORE_INDEX);

    float instS = 0.f, ceS = 0.f;
    if (v2) {
        float s = 0.f;
#pragma unroll
        for (int c = 0; c < NCHUNK; c++) s += g_s_inst[m * NCHUNK + c];
        float lse = (s > 0.f) ? (30.f + logf(s)) : -1e30f;
        int cnt = 0;
        float sum = 0.f;
#pragma unroll
        for (int c = 0; c < NCHUNK; c++) {
            int pc = g_pcnt[m * NCHUNK + c];
            cnt += pc;
            int pl = pc < CAPC ? pc : CAPC;
            for (int q = 0; q < pl; q++)
                sum += log1pf(expf(lse - g_posx[(m * NCHUNK + c) * CAPC + q]));
        }
        instS = sum / fmaxf((float)cnt, 1.f);
        if (v3) {
            float s2 = 0.f;
#pragma unroll
            for (int c = 0; c < NCHUNK; c++) s2 += g_s_reid[m * NCHUNK + c];
            ceS = (30.f + logf(s2)) - g_xt[m];
        }
    }
    float vals[5] = {instS, ceS, v ? 1.f : 0.f, v2 ? 1.f : 0.f, v3 ? 1.f : 0.f};
#pragma unroll
    for (int k = 0; k < 5; k++)
#pragma unroll
        for (int o = 16; o; o >>= 1)
            vals[k] += __shfl_xor_sync(0xffffffffu, vals[k], o);
    if (lane == 0)
        for (int k = 0; k < 5; k++) sred[wid][k] = vals[k];
    __syncthreads();
    if (tid == 0) {
        float tot[5] = {0, 0, 0, 0, 0};
        for (int w = 0; w < 4; w++)
            for (int k = 0; k < 5; k++) tot[k] += sred[w][k];
        for (int k = 0; k < 5; k++) g_part[blockIdx.x][k] = tot[k];
        __threadfence();
        int o = atomicAdd(&g_ticket, 1);
        s_last = (o == NMTILE - 1) ? 1 : 0;
    }
    __syncthreads();
    if (s_last) {
        float fcS = (tid < NCTA) ? g_fc[tid] : 0.f;
#pragma unroll
        for (int o = 16; o; o >>= 1) fcS += __shfl_xor_sync(0xffffffffu, fcS, o);
        if (lane == 0) sred[wid][0] = fcS;
        __syncthreads();
        if (tid == 0) {
            float fc = sred[0][0] + sred[1][0] + sred[2][0] + sred[3][0];
            float tot[5] = {0, 0, 0, 0, 0};
            for (int b = 0; b < NMTILE; b++)
                for (int k = 0; k < 5; k++) tot[k] += g_part[b][k];
            out[0] = fc / (fmaxf(tot[2], 1.f) * (float)NF)
                   + tot[1] / fmaxf(tot[4], 1.f)
                   + tot[0] / fmaxf(tot[3], 1.f);
        }
    }
}

// ---------------------------------------------------------------------------
extern "C" void kernel_launch(void* const* d_in, const int* in_sizes, int n_in,
                              void* d_out, int out_size) {
    const float* inputs      = (const float*)d_in[0];
    const int*   roi_label   = (const int*)d_in[1];
    const float* lut_inst    = (const float*)d_in[2];
    const float* reid_lut    = (const float*)d_in[3];
    const int*   reid_labels = (const int*)d_in[4];
    float* out = (float*)d_out;

    cudaFuncSetAttribute(main_kernel, cudaFuncAttributeMaxDynamicSharedMemorySize,
                         SMEM_TOTAL);

    convert_kernel<<<CONV_GRID, 256>>>(inputs, lut_inst, reid_lut, roi_label);
    main_kernel<<<dim3(NMTILE, NCHUNK), 512, SMEM_TOTAL>>>(roi_label, reid_labels);
    finalize_kernel<<<NMTILE, 128>>>(roi_label, reid_labels, out);
}

// round 15
// speedup vs baseline: 1.3414x; 1.0394x over previous
#include <cuda_runtime.h>
#include <cuda_fp16.h>
#include <math.h>
#include <stdint.h>

#define NB 4096
#define NF 256
#define NP 5000
#define NCHUNK 4
#define CHUNK_P 1280
#define NMTILE 32
#define NCTA (NMTILE * NCHUNK)        // 128
#define CAPC 16
#define IGNORE_INDEX 5554
#define AST 264                       // A smem row stride (halfs), 528B
#define BST 72                        // B smem row stride (halfs), 144B
#define A_BYTES (128 * AST * 2)       // 67584
#define B_STAGE (256 * BST * 2)       // 36864
#define NSTAGE 4
#define SM_META (A_BYTES + NSTAGE * B_STAGE)       // 215040
#define SM_RED  (SM_META + 4 * 128 * 4)            // 217088
#define SM_RLAB (SM_RED + 8 * 128 * 4)             // 221184
#define SMEM_TOTAL (SM_RLAB + CHUNK_P * 4)         // 226304
#define NI 40                         // 10 nt-tiles * 4 k-chunks

// ---------------- static scratch ----------------
__device__ __align__(16) __half g_inh[NB * NF];
__device__ __align__(16) __half g_lih[NP * NF];
__device__ __align__(16) __half g_rlh[NP * NF];
__device__ float g_s_inst[NB * NCHUNK];
__device__ float g_s_reid[NB * NCHUNK];
__device__ int   g_pcnt[NB * NCHUNK];
__device__ float g_posx[NB * NCHUNK * CAPC];
__device__ float g_xt[NB];
__device__ float g_fc[NCTA];
__device__ float g_part[NMTILE][5];
__device__ int   g_ticket;

// ---------------- helpers ----------------
__device__ __forceinline__ uint32_t smem_u32(const void* p) {
    uint32_t a;
    asm("{ .reg .u64 t; cvta.to.shared.u64 t, %1; cvt.u32.u64 %0, t; }"
        : "=r"(a) : "l"(p));
    return a;
}
__device__ __forceinline__ void cp16(uint32_t dst, const void* src, int sz) {
    asm volatile("cp.async.cg.shared.global [%0], [%1], 16, %2;"
                 :: "r"(dst), "l"(src), "r"(sz) : "memory");
}
#define CP_COMMIT() asm volatile("cp.async.commit_group;" ::: "memory")
#define CP_WAIT2()  asm volatile("cp.async.wait_group 2;" ::: "memory")

__device__ __forceinline__ void ldmx4(uint32_t* r, uint32_t addr) {
    asm volatile("ldmatrix.sync.aligned.m8n8.x4.shared.b16 {%0,%1,%2,%3}, [%4];"
                 : "=r"(r[0]), "=r"(r[1]), "=r"(r[2]), "=r"(r[3]) : "r"(addr));
}
__device__ __forceinline__ void mma16(float* c, const uint32_t* a,
                                      uint32_t b0, uint32_t b1) {
    asm("mma.sync.aligned.m16n8k16.row.col.f32.f16.f16.f32 "
        "{%0,%1,%2,%3}, {%4,%5,%6,%7}, {%8,%9}, {%0,%1,%2,%3};"
        : "+f"(c[0]), "+f"(c[1]), "+f"(c[2]), "+f"(c[3])
        : "r"(a[0]), "r"(a[1]), "r"(a[2]), "r"(a[3]), "r"(b0), "r"(b1));
}

__device__ __forceinline__ uint2 cvt2(float4 v) {
    uint2 o;
    half2 lo = __floats2half2_rn(v.x, v.y);
    half2 hi = __floats2half2_rn(v.z, v.w);
    o.x = *(uint32_t*)&lo;
    o.y = *(uint32_t*)&hi;
    return o;
}

// ---------------------------------------------------------------------------
// K0: flat grid-stride f32->f16 convert + ticket reset + fc partials.
// ---------------------------------------------------------------------------
#define T0 (NB * NF / 4)
#define T1 (NP * NF / 4)
#define TTOT (T0 + 2 * T1)
#define CONV_GRID 1184

__global__ void __launch_bounds__(256)
convert_kernel(const float* __restrict__ inp, const float* __restrict__ li,
               const float* __restrict__ rl, const int* __restrict__ roi_label)
{
    __shared__ float sred[8];
    int tid = threadIdx.x, wid = tid >> 5, lane = tid & 31;
    int idx = blockIdx.x * blockDim.x + tid;
    int stride = blockDim.x * gridDim.x;
    if (blockIdx.x == 0 && tid == 0) g_ticket = 0;

#pragma unroll 4
    for (int i = idx; i < TTOT; i += stride) {
        const float4* src;
        uint2* dst;
        int j;
        if (i < T0)           { src = (const float4*)inp; dst = (uint2*)g_inh; j = i; }
        else if (i < T0 + T1) { src = (const float4*)li;  dst = (uint2*)g_lih; j = i - T0; }
        else                  { src = (const float4*)rl;  dst = (uint2*)g_rlh; j = i - T0 - T1; }
        dst[j] = cvt2(src[j]);
    }

    if (blockIdx.x < NCTA) {
        int m0 = blockIdx.x * (NB / NCTA);
        float acc = 0.0f;
        for (int r = wid; r < NB / NCTA; r += 8) {
            int m = m0 + r;
            int t = roi_label[m] - 1;
            if (t >= 0) {
                const float4* a = (const float4*)(inp + (size_t)m * NF);
                const float4* b = (const float4*)(li + (size_t)t * NF);
                float s = 0.0f;
#pragma unroll
                for (int i = 0; i < 2; i++) {
                    float4 av = a[lane + 32 * i], bv = b[lane + 32 * i];
                    float dx = bv.x - av.x, dy = bv.y - av.y;
                    float dz = bv.z - av.z, dw = bv.w - av.w;
                    s += dx * dx + dy * dy + dz * dz + dw * dw;
                }
#pragma unroll
                for (int o = 16; o; o >>= 1) s += __shfl_xor_sync(0xffffffffu, s, o);
                acc += s;
            }
        }
        if (lane == 0) sred[wid] = acc;
        __syncthreads();
        if (tid == 0) {
            float s = 0.0f;
            for (int w = 0; w < 8; w++) s += sred[w];
            g_fc[blockIdx.x] = s;
        }
    }
}

// ---------------------------------------------------------------------------
// Main fused kernel: grid (32 m-tiles, 4 p-chunks) = 128 CTAs, 512 threads.
// 4-stage cp.async pipeline, ONE __syncthreads per iteration:
//   wait_group 2 -> barrier -> issue(i+3) into buf (i+3)&3 -> commit -> mma.
// ---------------------------------------------------------------------------
__global__ void __launch_bounds__(512, 1)
main_kernel(const int* __restrict__ roi_label, const int* __restrict__ reid_labels)
{
    extern __shared__ char smem[];
    char* sB = smem + A_BYTES;
    int*   s_lreid = (int*)(smem + SM_META);
    int*   s_lr    = s_lreid + 128;
    int*   s_v2    = s_lr + 128;
    int*   s_pcnt  = s_v2 + 128;
    float* s_red2  = (float*)(smem + SM_RED);    // [8][128]
    int*   s_rlab  = (int*)(smem + SM_RLAB);     // [CHUNK_P]

    const uint32_t sA_a = smem_u32(smem);
    const uint32_t sB_a = smem_u32(sB);

    int tid = threadIdx.x;
    int wid = tid >> 5, lane = tid & 31;
    int qid = lane >> 2, tg = lane & 3;
    int mw = wid >> 3, nw = wid & 7;
    int m0 = blockIdx.x * 128;
    int chunk = blockIdx.y;
    int pbase = chunk * CHUNK_P;

    if (tid < 128) {
        int m = m0 + tid;
        int t = roi_label[m] - 1;
        bool v = (t >= 0);
        int label = v ? t : 0;
        int lreid = reid_labels[label];
        s_lreid[tid] = lreid;
        s_lr[tid] = lreid > 0 ? lreid : 0;
        s_v2[tid] = (v && lreid >= 0) ? 1 : 0;
        s_pcnt[tid] = 0;
    }
    for (int j = tid; j < CHUNK_P; j += 512) {
        int p = pbase + j;
        s_rlab[j] = (p < NP) ? reid_labels[p] : (int)0x80000000;
    }

    // ---- stage A (f16, full 128x256) ----
    {
        const __half* Ain = g_inh + (size_t)m0 * NF;
#pragma unroll
        for (int j = 0; j < 8; j++) {
            int ci = tid + j * 512;
            int row = ci >> 5, c = ci & 31;
            cp16(sA_a + (uint32_t)(row * AST + c * 8) * 2, Ain + row * NF + c * 8, 16);
        }
    }
    auto issue_B = [&](int i, int buf) {
        int nt = i >> 2, kc = i & 3;
        const __half* lut = (nt < 5) ? g_lih : g_rlh;
        int p0 = pbase + (nt % 5) * 256;
        uint32_t dstBase = sB_a + (uint32_t)buf * B_STAGE;
#pragma unroll
        for (int j = 0; j < 4; j++) {
            int ci = tid + j * 512;
            int row = ci >> 3, c = ci & 7;
            int p = p0 + row;
            int pc = p < NP ? p : NP - 1;
            cp16(dstBase + (uint32_t)(row * BST + c * 8) * 2,
                 lut + (size_t)pc * NF + kc * 64 + c * 8, (p < NP) ? 16 : 0);
        }
    };
    issue_B(0, 0);
    CP_COMMIT();
    issue_B(1, 1);
    CP_COMMIT();
    issue_B(2, 2);
    CP_COMMIT();

    // ldmatrix lane bases
    uint32_t abase[4];
#pragma unroll
    for (int mf = 0; mf < 4; mf++)
        abase[mf] = sA_a + (uint32_t)((mw * 64 + mf * 16 + (lane & 15)) * AST
                                      + (lane >> 4) * 8) * 2;
    int noff = (lane & 7) + ((lane >> 4) << 3);
    uint32_t bbase = sB_a + (uint32_t)((nw * 32 + noff) * BST + ((lane & 8) ? 8 : 0)) * 2;

    float acc[4][4][4];
    float sacc[8];
#pragma unroll
    for (int q = 0; q < 8; q++) sacc[q] = 0.0f;

#pragma unroll 1
    for (int i = 0; i < NI; i++) {
        int nt = i >> 2, kc = i & 3, bufi = i & 3;
        if (kc == 0) {
#pragma unroll
            for (int mf = 0; mf < 4; mf++)
#pragma unroll
                for (int nf = 0; nf < 4; nf++)
#pragma unroll
                    for (int r = 0; r < 4; r++) acc[mf][nf][r] = 0.0f;
        }
        CP_WAIT2();
        __syncthreads();
        if (i + 3 < NI) issue_B(i + 3, (i + 3) & 3);
        CP_COMMIT();

        uint32_t bstage = bbase + (uint32_t)bufi * B_STAGE;
#pragma unroll
        for (int kk = 0; kk < 4; kk++) {
            uint32_t a[4][4], b[8];
            uint32_t akb = (uint32_t)(kc * 4 + kk) * 32;
#pragma unroll
            for (int mf = 0; mf < 4; mf++) ldmx4(a[mf], abase[mf] + akb);
            ldmx4(b,     bstage + kk * 32);
            ldmx4(b + 4, bstage + 16 * BST * 2 + kk * 32);
#pragma unroll
            for (int nf = 0; nf < 4; nf++)
#pragma unroll
                for (int mf = 0; mf < 4; mf++)
                    mma16(acc[mf][nf], a[mf], b[nf * 2], b[nf * 2 + 1]);
        }

        if (kc == 3) {
            // ---------------- epilogue for tile nt ----------------
            int j0 = (nt % 5) * 256;
            bool inst = (nt < 5);
#pragma unroll
            for (int nf = 0; nf < 4; nf++) {
                int jb = j0 + nw * 32 + nf * 8 + tg * 2;
                int pb = pbase + jb;
                bool ok0 = pb < NP, ok1 = (pb + 1) < NP;
                int rl0 = 0, rl1 = 0;
                if (inst) { rl0 = s_rlab[jb]; rl1 = s_rlab[jb + 1]; }
#pragma unroll
                for (int mf = 0; mf < 4; mf++) {
#pragma unroll
                    for (int h = 0; h < 2; h++) {
                        int lrow = mw * 64 + mf * 16 + h * 8 + qid;
                        int slot = mf * 2 + h;
                        float x0 = acc[mf][nf][h * 2 + 0] * 30.0f;
                        float x1 = acc[mf][nf][h * 2 + 1] * 30.0f;
                        if (inst) {
                            int lre = s_lreid[lrow];
                            if (ok0) {
                                if (rl0 == lre) {
                                    if (s_v2[lrow]) {
                                        int idx = atomicAdd(&s_pcnt[lrow], 1);
                                        if (idx < CAPC)
                                            g_posx[((m0 + lrow) * NCHUNK + chunk) * CAPC + idx] = x0;
                                    }
                                } else sacc[slot] += __expf(x0 - 30.0f);
                            }
                            if (ok1) {
                                if (rl1 == lre) {
                                    if (s_v2[lrow]) {
                                        int idx = atomicAdd(&s_pcnt[lrow], 1);
                                        if (idx < CAPC)
                                            g_posx[((m0 + lrow) * NCHUNK + chunk) * CAPC + idx] = x1;
                                    }
                                } else sacc[slot] += __expf(x1 - 30.0f);
                            }
                        } else {
                            if (ok0) {
                                sacc[slot] += __expf(x0 - 30.0f);
                                if (pb == s_lr[lrow]) g_xt[m0 + lrow] = x0;
                            }
                            if (ok1) {
                                sacc[slot] += __expf(x1 - 30.0f);
                                if (pb + 1 == s_lr[lrow]) g_xt[m0 + lrow] = x1;
                            }
                        }
                    }
                }
            }
            if (nt == 4 || nt == 9) {
                // cross-warp reduction -> one scalar per row
#pragma unroll
                for (int slot = 0; slot < 8; slot++) {
                    float vv = sacc[slot];
                    vv += __shfl_xor_sync(0xffffffffu, vv, 1);
                    vv += __shfl_xor_sync(0xffffffffu, vv, 2);
                    if (tg == 0) {
                        int mf = slot >> 1, h = slot & 1;
                        int lrow = mw * 64 + mf * 16 + h * 8 + qid;
                        s_red2[nw * 128 + lrow] = vv;
                    }
                    sacc[slot] = 0.0f;
                }
                __syncthreads();
                if (tid < 128) {
                    float t = 0.f;
#pragma unroll
                    for (int w = 0; w < 8; w++) t += s_red2[w * 128 + tid];
                    if (nt == 4) g_s_inst[(m0 + tid) * NCHUNK + chunk] = t;
                    else         g_s_reid[(m0 + tid) * NCHUNK + chunk] = t;
                }
            }
        }
    }

    __syncthreads();
    if (tid < 128)
        g_pcnt[(m0 + tid) * NCHUNK + chunk] = s_pcnt[tid];
}

// ---------------------------------------------------------------------------
// Finalize: 32 CTAs x 128 threads, one row per thread; last CTA sums all.
// ---------------------------------------------------------------------------
__global__ void __launch_bounds__(128)
finalize_kernel(const int* __restrict__ roi_label,
                const int* __restrict__ reid_labels, float* __restrict__ out)
{
    __shared__ float sred[4][5];
    __shared__ int s_last;
    int tid = threadIdx.x, wid = tid >> 5, lane = tid & 31;
    int m = blockIdx.x * 128 + tid;

    int t = roi_label[m] - 1;
    bool v = (t >= 0);
    int label = v ? t : 0;
    int lreid = reid_labels[label];
    bool v2 = v && (lreid >= 0);
    int lr = lreid > 0 ? lreid : 0;
    bool v3 = v2 && (lr != IGNORE_INDEX);

    float instS = 0.f, ceS = 0.f;
    if (v2) {
        float s = 0.f;
#pragma unroll
        for (int c = 0; c < NCHUNK; c++) s += g_s_inst[m * NCHUNK + c];
        float lse = (s > 0.f) ? (30.f + logf(s)) : -1e30f;
        int cnt = 0;
        float sum = 0.f;
#pragma unroll
        for (int c = 0; c < NCHUNK; c++) {
            int pc = g_pcnt[m * NCHUNK + c];
            cnt += pc;
            int pl = pc < CAPC ? pc : CAPC;
            for (int q = 0; q < pl; q++)
                sum += log1pf(expf(lse - g_posx[(m * NCHUNK + c) * CAPC + q]));
        }
        instS = sum / fmaxf((float)cnt, 1.f);
        if (v3) {
            float s2 = 0.f;
#pragma unroll
            for (int c = 0; c < NCHUNK; c++) s2 += g_s_reid[m * NCHUNK + c];
            ceS = (30.f + logf(s2)) - g_xt[m];
        }
    }
    float vals[5] = {instS, ceS, v ? 1.f : 0.f, v2 ? 1.f : 0.f, v3 ? 1.f : 0.f};
#pragma unroll
    for (int k = 0; k < 5; k++)
#pragma unroll
        for (int o = 16; o; o >>= 1)
            vals[k] += __shfl_xor_sync(0xffffffffu, vals[k], o);
    if (lane == 0)
        for (int k = 0; k < 5; k++) sred[wid][k] = vals[k];
    __syncthreads();
    if (tid == 0) {
        float tot[5] = {0, 0, 0, 0, 0};
        for (int w = 0; w < 4; w++)
            for (int k = 0; k < 5; k++) tot[k] += sred[w][k];
        for (int k = 0; k < 5; k++) g_part[blockIdx.x][k] = tot[k];
        __threadfence();
        int o = atomicAdd(&g_ticket, 1);
        s_last = (o == NMTILE - 1) ? 1 : 0;
    }
    __syncthreads();
    if (s_last) {
        float fcS = (tid < NCTA) ? g_fc[tid] : 0.f;
#pragma unroll
        for (int o = 16; o; o >>= 1) fcS += __shfl_xor_sync(0xffffffffu, fcS, o);
        if (lane == 0) sred[wid][0] = fcS;
        __syncthreads();
        if (tid == 0) {
            float fc = sred[0][0] + sred[1][0] + sred[2][0] + sred[3][0];
            float tot[5] = {0, 0, 0, 0, 0};
            for (int b = 0; b < NMTILE; b++)
                for (int k = 0; k < 5; k++) tot[k] += g_part[b][k];
            out[0] = fc / (fmaxf(tot[2], 1.f) * (float)NF)
                   + tot[1] / fmaxf(tot[4], 1.f)
                   + tot[0] / fmaxf(tot[3], 1.f);
        }
    }
}

// ---------------------------------------------------------------------------
extern "C" void kernel_launch(void* const* d_in, const int* in_sizes, int n_in,
                              void* d_out, int out_size) {
    const float* inputs      = (const float*)d_in[0];
    const int*   roi_label   = (const int*)d_in[1];
    const float* lut_inst    = (const float*)d_in[2];
    const float* reid_lut    = (const float*)d_in[3];
    const int*   reid_labels = (const int*)d_in[4];
    float* out = (float*)d_out;

    cudaFuncSetAttribute(main_kernel, cudaFuncAttributeMaxDynamicSharedMemorySize,
                         SMEM_TOTAL);

    convert_kernel<<<CONV_GRID, 256>>>(inputs, lut_inst, reid_lut, roi_label);
    main_kernel<<<dim3(NMTILE, NCHUNK), 512, SMEM_TOTAL>>>(roi_label, reid_labels);
    finalize_kernel<<<NMTILE, 128>>>(roi_label, reid_labels, out);
}

// round 16
// speedup vs baseline: 1.3452x; 1.0028x over previous
#include <cuda_runtime.h>
#include <cuda_fp16.h>
#include <math.h>
#include <stdint.h>

#define NB 4096
#define NF 256
#define NP 5000
#define NCHUNK 4
#define CHUNK_P 1280
#define NMTILE 32
#define NCTA (NMTILE * NCHUNK)        // 128
#define CAPC 16
#define IGNORE_INDEX 5554
#define AST 264                       // A smem row stride (halfs), 528B
#define BST 72                        // B smem row stride (halfs), 144B
#define A_BYTES (128 * AST * 2)       // 67584
#define B_STAGE (256 * BST * 2)       // 36864
#define NSTAGE 4
#define SM_META (A_BYTES + NSTAGE * B_STAGE)       // 215040
#define SM_RED  (SM_META + 4 * 128 * 4)            // 217088
#define SM_RLAB (SM_RED + 8 * 128 * 4)             // 221184
#define SMEM_TOTAL (SM_RLAB + CHUNK_P * 4)         // 226304
#define NI 40                         // 10 nt-tiles * 4 k-chunks

// ---------------- static scratch ----------------
__device__ __align__(16) __half g_inh[NB * NF];
__device__ __align__(16) __half g_lih[NP * NF];
__device__ __align__(16) __half g_rlh[NP * NF];
__device__ float g_s_inst[NB * NCHUNK];
__device__ float g_s_reid[NB * NCHUNK];
__device__ int   g_pcnt[NB * NCHUNK];
__device__ float g_posx[NB * NCHUNK * CAPC];
__device__ float g_xt[NB];
__device__ float g_fc[NCTA];
__device__ float g_part[NMTILE][5];
__device__ int   g_ticket;

// ---------------- helpers ----------------
__device__ __forceinline__ uint32_t smem_u32(const void* p) {
    uint32_t a;
    asm("{ .reg .u64 t; cvta.to.shared.u64 t, %1; cvt.u32.u64 %0, t; }"
        : "=r"(a) : "l"(p));
    return a;
}
__device__ __forceinline__ void cp16(uint32_t dst, const void* src, int sz) {
    asm volatile("cp.async.cg.shared.global [%0], [%1], 16, %2;"
                 :: "r"(dst), "l"(src), "r"(sz) : "memory");
}
#define CP_COMMIT() asm volatile("cp.async.commit_group;" ::: "memory")
#define CP_WAIT2()  asm volatile("cp.async.wait_group 2;" ::: "memory")

__device__ __forceinline__ void ldmx4(uint32_t* r, uint32_t addr) {
    asm volatile("ldmatrix.sync.aligned.m8n8.x4.shared.b16 {%0,%1,%2,%3}, [%4];"
                 : "=r"(r[0]), "=r"(r[1]), "=r"(r[2]), "=r"(r[3]) : "r"(addr));
}
__device__ __forceinline__ void mma16(float* c, const uint32_t* a,
                                      uint32_t b0, uint32_t b1) {
    asm("mma.sync.aligned.m16n8k16.row.col.f32.f16.f16.f32 "
        "{%0,%1,%2,%3}, {%4,%5,%6,%7}, {%8,%9}, {%0,%1,%2,%3};"
        : "+f"(c[0]), "+f"(c[1]), "+f"(c[2]), "+f"(c[3])
        : "r"(a[0]), "r"(a[1]), "r"(a[2]), "r"(a[3]), "r"(b0), "r"(b1));
}

__device__ __forceinline__ uint4 cvt4(float4 v0, float4 v1) {
    uint4 o;
    half2 a = __floats2half2_rn(v0.x, v0.y);
    half2 b = __floats2half2_rn(v0.z, v0.w);
    half2 c = __floats2half2_rn(v1.x, v1.y);
    half2 d = __floats2half2_rn(v1.z, v1.w);
    o.x = *(uint32_t*)&a;
    o.y = *(uint32_t*)&b;
    o.z = *(uint32_t*)&c;
    o.w = *(uint32_t*)&d;
    return o;
}

// ---------------------------------------------------------------------------
// K0: flat grid-stride f32->f16 convert (8 floats / step: 2 LDG.128 + 1
// STG.128) + ticket reset + fc partials.
// ---------------------------------------------------------------------------
#define U0 (NB * NF / 8)
#define U1 (NP * NF / 8)
#define UTOT (U0 + 2 * U1)
#define CONV_GRID 1184

__global__ void __launch_bounds__(256)
convert_kernel(const float* __restrict__ inp, const float* __restrict__ li,
               const float* __restrict__ rl, const int* __restrict__ roi_label)
{
    __shared__ float sred[8];
    int tid = threadIdx.x, wid = tid >> 5, lane = tid & 31;
    int idx = blockIdx.x * blockDim.x + tid;
    int stride = blockDim.x * gridDim.x;
    if (blockIdx.x == 0 && tid == 0) g_ticket = 0;

#pragma unroll 4
    for (int i = idx; i < UTOT; i += stride) {
        const float4* src;
        uint4* dst;
        int j;
        if (i < U0)           { src = (const float4*)inp; dst = (uint4*)g_inh; j = i; }
        else if (i < U0 + U1) { src = (const float4*)li;  dst = (uint4*)g_lih; j = i - U0; }
        else                  { src = (const float4*)rl;  dst = (uint4*)g_rlh; j = i - U0 - U1; }
        float4 v0 = src[2 * j];
        float4 v1 = src[2 * j + 1];
        dst[j] = cvt4(v0, v1);
    }

    if (blockIdx.x < NCTA) {
        int m0 = blockIdx.x * (NB / NCTA);
        float acc = 0.0f;
        for (int r = wid; r < NB / NCTA; r += 8) {
            int m = m0 + r;
            int t = roi_label[m] - 1;
            if (t >= 0) {
                const float4* a = (const float4*)(inp + (size_t)m * NF);
                const float4* b = (const float4*)(li + (size_t)t * NF);
                float s = 0.0f;
#pragma unroll
                for (int i = 0; i < 2; i++) {
                    float4 av = a[lane + 32 * i], bv = b[lane + 32 * i];
                    float dx = bv.x - av.x, dy = bv.y - av.y;
                    float dz = bv.z - av.z, dw = bv.w - av.w;
                    s += dx * dx + dy * dy + dz * dz + dw * dw;
                }
#pragma unroll
                for (int o = 16; o; o >>= 1) s += __shfl_xor_sync(0xffffffffu, s, o);
                acc += s;
            }
        }
        if (lane == 0) sred[wid] = acc;
        __syncthreads();
        if (tid == 0) {
            float s = 0.0f;
            for (int w = 0; w < 8; w++) s += sred[w];
            g_fc[blockIdx.x] = s;
        }
    }
}

// ---------------------------------------------------------------------------
// Main fused kernel: grid (32 m-tiles, 4 p-chunks) = 128 CTAs, 512 threads.
// 4-stage cp.async pipeline, ONE __syncthreads per iteration:
//   wait_group 2 -> barrier -> issue(i+3) into buf (i+3)&3 -> commit -> mma.
// ---------------------------------------------------------------------------
__global__ void __launch_bounds__(512, 1)
main_kernel(const int* __restrict__ roi_label, const int* __restrict__ reid_labels)
{
    extern __shared__ char smem[];
    char* sB = smem + A_BYTES;
    int*   s_lreid = (int*)(smem + SM_META);
    int*   s_lr    = s_lreid + 128;
    int*   s_v2    = s_lr + 128;
    int*   s_pcnt  = s_v2 + 128;
    float* s_red2  = (float*)(smem + SM_RED);    // [8][128]
    int*   s_rlab  = (int*)(smem + SM_RLAB);     // [CHUNK_P]

    const uint32_t sA_a = smem_u32(smem);
    const uint32_t sB_a = smem_u32(sB);

    int tid = threadIdx.x;
    int wid = tid >> 5, lane = tid & 31;
    int qid = lane >> 2, tg = lane & 3;
    int mw = wid >> 3, nw = wid & 7;
    int m0 = blockIdx.x * 128;
    int chunk = blockIdx.y;
    int pbase = chunk * CHUNK_P;

    if (tid < 128) {
        int m = m0 + tid;
        int t = roi_label[m] - 1;
        bool v = (t >= 0);
        int label = v ? t : 0;
        int lreid = reid_labels[label];
        s_lreid[tid] = lreid;
        s_lr[tid] = lreid > 0 ? lreid : 0;
        s_v2[tid] = (v && lreid >= 0) ? 1 : 0;
        s_pcnt[tid] = 0;
    }
    for (int j = tid; j < CHUNK_P; j += 512) {
        int p = pbase + j;
        s_rlab[j] = (p < NP) ? reid_labels[p] : (int)0x80000000;
    }

    // ---- stage A (f16, full 128x256) ----
    {
        const __half* Ain = g_inh + (size_t)m0 * NF;
#pragma unroll
        for (int j = 0; j < 8; j++) {
            int ci = tid + j * 512;
            int row = ci >> 5, c = ci & 31;
            cp16(sA_a + (uint32_t)(row * AST + c * 8) * 2, Ain + row * NF + c * 8, 16);
        }
    }
    auto issue_B = [&](int i, int buf) {
        int nt = i >> 2, kc = i & 3;
        const __half* lut = (nt < 5) ? g_lih : g_rlh;
        int p0 = pbase + (nt % 5) * 256;
        uint32_t dstBase = sB_a + (uint32_t)buf * B_STAGE;
#pragma unroll
        for (int j = 0; j < 4; j++) {
            int ci = tid + j * 512;
            int row = ci >> 3, c = ci & 7;
            int p = p0 + row;
            int pc = p < NP ? p : NP - 1;
            cp16(dstBase + (uint32_t)(row * BST + c * 8) * 2,
                 lut + (size_t)pc * NF + kc * 64 + c * 8, (p < NP) ? 16 : 0);
        }
    };
    issue_B(0, 0);
    CP_COMMIT();
    issue_B(1, 1);
    CP_COMMIT();
    issue_B(2, 2);
    CP_COMMIT();

    // ldmatrix lane bases
    uint32_t abase[4];
#pragma unroll
    for (int mf = 0; mf < 4; mf++)
        abase[mf] = sA_a + (uint32_t)((mw * 64 + mf * 16 + (lane & 15)) * AST
                                      + (lane >> 4) * 8) * 2;
    int noff = (lane & 7) + ((lane >> 4) << 3);
    uint32_t bbase = sB_a + (uint32_t)((nw * 32 + noff) * BST + ((lane & 8) ? 8 : 0)) * 2;

    float acc[4][4][4];
    float sacc[8];
#pragma unroll
    for (int q = 0; q < 8; q++) sacc[q] = 0.0f;

#pragma unroll 1
    for (int i = 0; i < NI; i++) {
        int nt = i >> 2, kc = i & 3, bufi = i & 3;
        if (kc == 0) {
#pragma unroll
            for (int mf = 0; mf < 4; mf++)
#pragma unroll
                for (int nf = 0; nf < 4; nf++)
#pragma unroll
                    for (int r = 0; r < 4; r++) acc[mf][nf][r] = 0.0f;
        }
        CP_WAIT2();
        __syncthreads();
        if (i + 3 < NI) issue_B(i + 3, (i + 3) & 3);
        CP_COMMIT();

        uint32_t bstage = bbase + (uint32_t)bufi * B_STAGE;
#pragma unroll
        for (int kk = 0; kk < 4; kk++) {
            uint32_t a[4][4], b[8];
            uint32_t akb = (uint32_t)(kc * 4 + kk) * 32;
#pragma unroll
            for (int mf = 0; mf < 4; mf++) ldmx4(a[mf], abase[mf] + akb);
            ldmx4(b,     bstage + kk * 32);
            ldmx4(b + 4, bstage + 16 * BST * 2 + kk * 32);
#pragma unroll
            for (int nf = 0; nf < 4; nf++)
#pragma unroll
                for (int mf = 0; mf < 4; mf++)
                    mma16(acc[mf][nf], a[mf], b[nf * 2], b[nf * 2 + 1]);
        }

        if (kc == 3) {
            // ---------------- epilogue for tile nt ----------------
            int j0 = (nt % 5) * 256;
            bool inst = (nt < 5);
#pragma unroll
            for (int nf = 0; nf < 4; nf++) {
                int jb = j0 + nw * 32 + nf * 8 + tg * 2;
                int pb = pbase + jb;
                bool ok0 = pb < NP, ok1 = (pb + 1) < NP;
                int rl0 = 0, rl1 = 0;
                if (inst) { rl0 = s_rlab[jb]; rl1 = s_rlab[jb + 1]; }
#pragma unroll
                for (int mf = 0; mf < 4; mf++) {
#pragma unroll
                    for (int h = 0; h < 2; h++) {
                        int lrow = mw * 64 + mf * 16 + h * 8 + qid;
                        int slot = mf * 2 + h;
                        float x0 = acc[mf][nf][h * 2 + 0] * 30.0f;
                        float x1 = acc[mf][nf][h * 2 + 1] * 30.0f;
                        if (inst) {
                            int lre = s_lreid[lrow];
                            if (ok0) {
                                if (rl0 == lre) {
                                    if (s_v2[lrow]) {
                                        int idx = atomicAdd(&s_pcnt[lrow], 1);
                                        if (idx < CAPC)
                                            g_posx[((m0 + lrow) * NCHUNK + chunk) * CAPC + idx] = x0;
                                    }
                                } else sacc[slot] += __expf(x0 - 30.0f);
                            }
                            if (ok1) {
                                if (rl1 == lre) {
                                    if (s_v2[lrow]) {
                                        int idx = atomicAdd(&s_pcnt[lrow], 1);
                                        if (idx < CAPC)
                                            g_posx[((m0 + lrow) * NCHUNK + chunk) * CAPC + idx] = x1;
                                    }
                                } else sacc[slot] += __expf(x1 - 30.0f);
                            }
                        } else {
                            if (ok0) {
                                sacc[slot] += __expf(x0 - 30.0f);
                                if (pb == s_lr[lrow]) g_xt[m0 + lrow] = x0;
                            }
                            if (ok1) {
                                sacc[slot] += __expf(x1 - 30.0f);
                                if (pb + 1 == s_lr[lrow]) g_xt[m0 + lrow] = x1;
                            }
                        }
                    }
                }
            }
            if (nt == 4 || nt == 9) {
                // cross-warp reduction -> one scalar per row
#pragma unroll
                for (int slot = 0; slot < 8; slot++) {
                    float vv = sacc[slot];
                    vv += __shfl_xor_sync(0xffffffffu, vv, 1);
                    vv += __shfl_xor_sync(0xffffffffu, vv, 2);
                    if (tg == 0) {
                        int mf = slot >> 1, h = slot & 1;
                        int lrow = mw * 64 + mf * 16 + h * 8 + qid;
                        s_red2[nw * 128 + lrow] = vv;
                    }
                    sacc[slot] = 0.0f;
                }
                __syncthreads();
                if (tid < 128) {
                    float t = 0.f;
#pragma unroll
                    for (int w = 0; w < 8; w++) t += s_red2[w * 128 + tid];
                    if (nt == 4) g_s_inst[(m0 + tid) * NCHUNK + chunk] = t;
                    else         g_s_reid[(m0 + tid) * NCHUNK + chunk] = t;
                }
            }
        }
    }

    __syncthreads();
    if (tid < 128)
        g_pcnt[(m0 + tid) * NCHUNK + chunk] = s_pcnt[tid];
}

// ---------------------------------------------------------------------------
// Finalize: 32 CTAs x 128 threads, one row per thread; last CTA sums all.
// ---------------------------------------------------------------------------
__global__ void __launch_bounds__(128)
finalize_kernel(const int* __restrict__ roi_label,
                const int* __restrict__ reid_labels, float* __restrict__ out)
{
    __shared__ float sred[4][5];
    __shared__ int s_last;
    int tid = threadIdx.x, wid = tid >> 5, lane = tid & 31;
    int m = blockIdx.x * 128 + tid;

    int t = roi_label[m] - 1;
    bool v = (t >= 0);
    int label = v ? t : 0;
    int lreid = reid_labels[label];
    bool v2 = v && (lreid >= 0);
    int lr = lreid > 0 ? lreid : 0;
    bool v3 = v2 && (lr != IGNORE_INDEX);

    float instS = 0.f, ceS = 0.f;
    if (v2) {
        float s = 0.f;
#pragma unroll
        for (int c = 0; c < NCHUNK; c++) s += g_s_inst[m * NCHUNK + c];
        float lse = (s > 0.f) ? (30.f + logf(s)) : -1e30f;
        int cnt = 0;
        float sum = 0.f;
#pragma unroll
        for (int c = 0; c < NCHUNK; c++) {
            int pc = g_pcnt[m * NCHUNK + c];
            cnt += pc;
            int pl = pc < CAPC ? pc : CAPC;
            for (int q = 0; q < pl; q++)
                sum += log1pf(expf(lse - g_posx[(m * NCHUNK + c) * CAPC + q]));
        }
        instS = sum / fmaxf((float)cnt, 1.f);
        if (v3) {
            float s2 = 0.f;
#pragma unroll
            for (int c = 0; c < NCHUNK; c++) s2 += g_s_reid[m * NCHUNK + c];
            ceS = (30.f + logf(s2)) - g_xt[m];
        }
    }
    float vals[5] = {instS, ceS, v ? 1.f : 0.f, v2 ? 1.f : 0.f, v3 ? 1.f : 0.f};
#pragma unroll
    for (int k = 0; k < 5; k++)
#pragma unroll
        for (int o = 16; o; o >>= 1)
            vals[k] += __shfl_xor_sync(0xffffffffu, vals[k], o);
    if (lane == 0)
        for (int k = 0; k < 5; k++) sred[wid][k] = vals[k];
    __syncthreads();
    if (tid == 0) {
        float tot[5] = {0, 0, 0, 0, 0};
        for (int w = 0; w < 4; w++)
            for (int k = 0; k < 5; k++) tot[k] += sred[w][k];
        for (int k = 0; k < 5; k++) g_part[blockIdx.x][k] = tot[k];
        __threadfence();
        int o = atomicAdd(&g_ticket, 1);
        s_last = (o == NMTILE - 1) ? 1 : 0;
    }
    __syncthreads();
    if (s_last) {
        float fcS = (tid < NCTA) ? g_fc[tid] : 0.f;
#pragma unroll
        for (int o = 16; o; o >>= 1) fcS += __shfl_xor_sync(0xffffffffu, fcS, o);
        if (lane == 0) sred[wid][0] = fcS;
        __syncthreads();
        if (tid == 0) {
            float fc = sred[0][0] + sred[1][0] + sred[2][0] + sred[3][0];
            float tot[5] = {0, 0, 0, 0, 0};
            for (int b = 0; b < NMTILE; b++)
                for (int k = 0; k < 5; k++) tot[k] += g_part[b][k];
            out[0] = fc / (fmaxf(tot[2], 1.f) * (float)NF)
                   + tot[1] / fmaxf(tot[4], 1.f)
                   + tot[0] / fmaxf(tot[3], 1.f);
        }
    }
}

// ---------------------------------------------------------------------------
extern "C" void kernel_launch(void* const* d_in, const int* in_sizes, int n_in,
                              void* d_out, int out_size) {
    const float* inputs      = (const float*)d_in[0];
    const int*   roi_label   = (const int*)d_in[1];
    const float* lut_inst    = (const float*)d_in[2];
    const float* reid_lut    = (const float*)d_in[3];
    const int*   reid_labels = (const int*)d_in[4];
    float* out = (float*)d_out;

    cudaFuncSetAttribute(main_kernel, cudaFuncAttributeMaxDynamicSharedMemorySize,
                         SMEM_TOTAL);

    convert_kernel<<<CONV_GRID, 256>>>(inputs, lut_inst, reid_lut, roi_label);
    main_kernel<<<dim3(NMTILE, NCHUNK), 512, SMEM_TOTAL>>>(roi_label, reid_labels);
    finalize_kernel<<<NMTILE, 128>>>(roi_label, reid_labels, out);
}

// round 17
// speedup vs baseline: 1.3660x; 1.0155x over previous
#include <cuda_runtime.h>
#include <cuda_fp16.h>
#include <math.h>
#include <stdint.h>

#define NB 4096
#define NF 256
#define NP 5000
#define NCHUNK 4
#define CHUNK_P 1280
#define NMTILE 32
#define NCTA (NMTILE * NCHUNK)        // 128
#define NFCBLK 1024
#define CAPC 16
#define IGNORE_INDEX 5554
#define AST 264                       // A smem row stride (halfs), 528B
#define BST 72                        // B smem row stride (halfs), 144B
#define A_BYTES (128 * AST * 2)       // 67584
#define B_STAGE (256 * BST * 2)       // 36864
#define NSTAGE 4
#define SM_META (A_BYTES + NSTAGE * B_STAGE)       // 215040
#define SM_RED  (SM_META + 4 * 128 * 4)            // 217088
#define SM_RLAB (SM_RED + 8 * 128 * 4)             // 221184
#define SMEM_TOTAL (SM_RLAB + CHUNK_P * 4)         // 226304
#define NI 40                         // 10 nt-tiles * 4 k-chunks

// ---------------- static scratch ----------------
__device__ __align__(16) __half g_inh[NB * NF];
__device__ __align__(16) __half g_lih[NP * NF];
__device__ __align__(16) __half g_rlh[NP * NF];
__device__ float g_s_inst[NB * NCHUNK];
__device__ float g_s_reid[NB * NCHUNK];
__device__ int   g_pcnt[NB * NCHUNK];
__device__ float g_posx[NB * NCHUNK * CAPC];
__device__ float g_xt[NB];
__device__ float g_fc[NFCBLK];
__device__ float g_part[NMTILE][5];
__device__ int   g_ticket;

// ---------------- helpers ----------------
__device__ __forceinline__ uint32_t smem_u32(const void* p) {
    uint32_t a;
    asm("{ .reg .u64 t; cvta.to.shared.u64 t, %1; cvt.u32.u64 %0, t; }"
        : "=r"(a) : "l"(p));
    return a;
}
__device__ __forceinline__ void cp16(uint32_t dst, const void* src, int sz) {
    asm volatile("cp.async.cg.shared.global [%0], [%1], 16, %2;"
                 :: "r"(dst), "l"(src), "r"(sz) : "memory");
}
#define CP_COMMIT() asm volatile("cp.async.commit_group;" ::: "memory")
#define CP_WAIT2()  asm volatile("cp.async.wait_group 2;" ::: "memory")

__device__ __forceinline__ void ldmx4(uint32_t* r, uint32_t addr) {
    asm volatile("ldmatrix.sync.aligned.m8n8.x4.shared.b16 {%0,%1,%2,%3}, [%4];"
                 : "=r"(r[0]), "=r"(r[1]), "=r"(r[2]), "=r"(r[3]) : "r"(addr));
}
__device__ __forceinline__ void mma16(float* c, const uint32_t* a,
                                      uint32_t b0, uint32_t b1) {
    asm("mma.sync.aligned.m16n8k16.row.col.f32.f16.f16.f32 "
        "{%0,%1,%2,%3}, {%4,%5,%6,%7}, {%8,%9}, {%0,%1,%2,%3};"
        : "+f"(c[0]), "+f"(c[1]), "+f"(c[2]), "+f"(c[3])
        : "r"(a[0]), "r"(a[1]), "r"(a[2]), "r"(a[3]), "r"(b0), "r"(b1));
}

__device__ __forceinline__ uint4 cvt4(float4 v0, float4 v1) {
    uint4 o;
    half2 a = __floats2half2_rn(v0.x, v0.y);
    half2 b = __floats2half2_rn(v0.z, v0.w);
    half2 c = __floats2half2_rn(v1.x, v1.y);
    half2 d = __floats2half2_rn(v1.z, v1.w);
    o.x = *(uint32_t*)&a;
    o.y = *(uint32_t*)&b;
    o.z = *(uint32_t*)&c;
    o.w = *(uint32_t*)&d;
    return o;
}

// ---------------------------------------------------------------------------
// K0: flat grid-stride f32->f16 convert (8 floats / step) + ticket reset +
// fc partials spread over 1024 CTAs (4 rows each, 2 warps per row).
// ---------------------------------------------------------------------------
#define U0 (NB * NF / 8)
#define U1 (NP * NF / 8)
#define UTOT (U0 + 2 * U1)
#define CONV_GRID 1184

__global__ void __launch_bounds__(256)
convert_kernel(const float* __restrict__ inp, const float* __restrict__ li,
               const float* __restrict__ rl, const int* __restrict__ roi_label)
{
    __shared__ float sred[8];
    int tid = threadIdx.x, wid = tid >> 5, lane = tid & 31;
    int idx = blockIdx.x * blockDim.x + tid;
    int stride = blockDim.x * gridDim.x;
    if (blockIdx.x == 0 && tid == 0) g_ticket = 0;

#pragma unroll 4
    for (int i = idx; i < UTOT; i += stride) {
        const float4* src;
        uint4* dst;
        int j;
        if (i < U0)           { src = (const float4*)inp; dst = (uint4*)g_inh; j = i; }
        else if (i < U0 + U1) { src = (const float4*)li;  dst = (uint4*)g_lih; j = i - U0; }
        else                  { src = (const float4*)rl;  dst = (uint4*)g_rlh; j = i - U0 - U1; }
        float4 v0 = src[2 * j];
        float4 v1 = src[2 * j + 1];
        dst[j] = cvt4(v0, v1);
    }

    // fc: 4 rows per CTA, 2 warps per row (64 float4 lanes = 256 floats)
    if (blockIdx.x < NFCBLK) {
        int m = blockIdx.x * 4 + (wid >> 1);
        int part = wid & 1;
        int t = roi_label[m] - 1;
        float s = 0.0f;
        if (t >= 0) {
            const float4* a = (const float4*)(inp + (size_t)m * NF);
            const float4* b = (const float4*)(li + (size_t)t * NF);
            float4 av = a[part * 32 + lane], bv = b[part * 32 + lane];
            float dx = bv.x - av.x, dy = bv.y - av.y;
            float dz = bv.z - av.z, dw = bv.w - av.w;
            s = dx * dx + dy * dy + dz * dz + dw * dw;
        }
#pragma unroll
        for (int o = 16; o; o >>= 1) s += __shfl_xor_sync(0xffffffffu, s, o);
        if (lane == 0) sred[wid] = s;
        __syncthreads();
        if (tid == 0) {
            float tot = 0.0f;
            for (int w = 0; w < 8; w++) tot += sred[w];
            g_fc[blockIdx.x] = tot;
        }
    }
}

// ---------------------------------------------------------------------------
// Main fused kernel: grid (32 m-tiles, 4 p-chunks) = 128 CTAs, 512 threads.
// 4-stage cp.async pipeline, ONE __syncthreads per iteration.
// ---------------------------------------------------------------------------
__global__ void __launch_bounds__(512, 1)
main_kernel(const int* __restrict__ roi_label, const int* __restrict__ reid_labels)
{
    extern __shared__ char smem[];
    char* sB = smem + A_BYTES;
    int*   s_lreid = (int*)(smem + SM_META);
    int*   s_lr    = s_lreid + 128;
    int*   s_v2    = s_lr + 128;
    int*   s_pcnt  = s_v2 + 128;
    float* s_red2  = (float*)(smem + SM_RED);    // [8][128]
    int*   s_rlab  = (int*)(smem + SM_RLAB);     // [CHUNK_P]

    const uint32_t sA_a = smem_u32(smem);
    const uint32_t sB_a = smem_u32(sB);

    int tid = threadIdx.x;
    int wid = tid >> 5, lane = tid & 31;
    int qid = lane >> 2, tg = lane & 3;
    int mw = wid >> 3, nw = wid & 7;
    int m0 = blockIdx.x * 128;
    int chunk = blockIdx.y;
    int pbase = chunk * CHUNK_P;

    if (tid < 128) {
        int m = m0 + tid;
        int t = roi_label[m] - 1;
        bool v = (t >= 0);
        int label = v ? t : 0;
        int lreid = reid_labels[label];
        s_lreid[tid] = lreid;
        s_lr[tid] = lreid > 0 ? lreid : 0;
        s_v2[tid] = (v && lreid >= 0) ? 1 : 0;
        s_pcnt[tid] = 0;
    }
    for (int j = tid; j < CHUNK_P; j += 512) {
        int p = pbase + j;
        s_rlab[j] = (p < NP) ? reid_labels[p] : (int)0x80000000;
    }

    // ---- stage A (f16, full 128x256) ----
    {
        const __half* Ain = g_inh + (size_t)m0 * NF;
#pragma unroll
        for (int j = 0; j < 8; j++) {
            int ci = tid + j * 512;
            int row = ci >> 5, c = ci & 31;
            cp16(sA_a + (uint32_t)(row * AST + c * 8) * 2, Ain + row * NF + c * 8, 16);
        }
    }
    auto issue_B = [&](int i, int buf) {
        int nt = i >> 2, kc = i & 3;
        const __half* lut = (nt < 5) ? g_lih : g_rlh;
        int p0 = pbase + (nt % 5) * 256;
        uint32_t dstBase = sB_a + (uint32_t)buf * B_STAGE;
#pragma unroll
        for (int j = 0; j < 4; j++) {
            int ci = tid + j * 512;
            int row = ci >> 3, c = ci & 7;
            int p = p0 + row;
            int pc = p < NP ? p : NP - 1;
            cp16(dstBase + (uint32_t)(row * BST + c * 8) * 2,
                 lut + (size_t)pc * NF + kc * 64 + c * 8, (p < NP) ? 16 : 0);
        }
    };
    issue_B(0, 0);
    CP_COMMIT();
    issue_B(1, 1);
    CP_COMMIT();
    issue_B(2, 2);
    CP_COMMIT();

    // ldmatrix lane bases
    uint32_t abase[4];
#pragma unroll
    for (int mf = 0; mf < 4; mf++)
        abase[mf] = sA_a + (uint32_t)((mw * 64 + mf * 16 + (lane & 15)) * AST
                                      + (lane >> 4) * 8) * 2;
    int noff = (lane & 7) + ((lane >> 4) << 3);
    uint32_t bbase = sB_a + (uint32_t)((nw * 32 + noff) * BST + ((lane & 8) ? 8 : 0)) * 2;

    float acc[4][4][4];
    float sacc[8];
#pragma unroll
    for (int q = 0; q < 8; q++) sacc[q] = 0.0f;

#pragma unroll 1
    for (int i = 0; i < NI; i++) {
        int nt = i >> 2, kc = i & 3, bufi = i & 3;
        if (kc == 0) {
#pragma unroll
            for (int mf = 0; mf < 4; mf++)
#pragma unroll
                for (int nf = 0; nf < 4; nf++)
#pragma unroll
                    for (int r = 0; r < 4; r++) acc[mf][nf][r] = 0.0f;
        }
        CP_WAIT2();
        __syncthreads();
        if (i + 3 < NI) issue_B(i + 3, (i + 3) & 3);
        CP_COMMIT();

        uint32_t bstage = bbase + (uint32_t)bufi * B_STAGE;
#pragma unroll
        for (int kk = 0; kk < 4; kk++) {
            uint32_t a[4][4], b[8];
            uint32_t akb = (uint32_t)(kc * 4 + kk) * 32;
#pragma unroll
            for (int mf = 0; mf < 4; mf++) ldmx4(a[mf], abase[mf] + akb);
            ldmx4(b,     bstage + kk * 32);
            ldmx4(b + 4, bstage + 16 * BST * 2 + kk * 32);
#pragma unroll
            for (int nf = 0; nf < 4; nf++)
#pragma unroll
                for (int mf = 0; mf < 4; mf++)
                    mma16(acc[mf][nf], a[mf], b[nf * 2], b[nf * 2 + 1]);
        }

        if (kc == 3) {
            // ---------------- epilogue for tile nt ----------------
            int j0 = (nt % 5) * 256;
            bool inst = (nt < 5);
#pragma unroll
            for (int nf = 0; nf < 4; nf++) {
                int jb = j0 + nw * 32 + nf * 8 + tg * 2;
                int pb = pbase + jb;
                bool ok0 = pb < NP, ok1 = (pb + 1) < NP;
                int rl0 = 0, rl1 = 0;
                if (inst) { rl0 = s_rlab[jb]; rl1 = s_rlab[jb + 1]; }
#pragma unroll
                for (int mf = 0; mf < 4; mf++) {
#pragma unroll
                    for (int h = 0; h < 2; h++) {
                        int lrow = mw * 64 + mf * 16 + h * 8 + qid;
                        int slot = mf * 2 + h;
                        float x0 = acc[mf][nf][h * 2 + 0] * 30.0f;
                        float x1 = acc[mf][nf][h * 2 + 1] * 30.0f;
                        if (inst) {
                            int lre = s_lreid[lrow];
                            if (ok0) {
                                if (rl0 == lre) {
                                    if (s_v2[lrow]) {
                                        int idx = atomicAdd(&s_pcnt[lrow], 1);
                                        if (idx < CAPC)
                                            g_posx[((m0 + lrow) * NCHUNK + chunk) * CAPC + idx] = x0;
                                    }
                                } else sacc[slot] += __expf(x0 - 30.0f);
                            }
                            if (ok1) {
                                if (rl1 == lre) {
                                    if (s_v2[lrow]) {
                                        int idx = atomicAdd(&s_pcnt[lrow], 1);
                                        if (idx < CAPC)
                                            g_posx[((m0 + lrow) * NCHUNK + chunk) * CAPC + idx] = x1;
                                    }
                                } else sacc[slot] += __expf(x1 - 30.0f);
                            }
                        } else {
                            if (ok0) {
                                sacc[slot] += __expf(x0 - 30.0f);
                                if (pb == s_lr[lrow]) g_xt[m0 + lrow] = x0;
                            }
                            if (ok1) {
                                sacc[slot] += __expf(x1 - 30.0f);
                                if (pb + 1 == s_lr[lrow]) g_xt[m0 + lrow] = x1;
                            }
                        }
                    }
                }
            }
            if (nt == 4 || nt == 9) {
                // cross-warp reduction -> one scalar per row
#pragma unroll
                for (int slot = 0; slot < 8; slot++) {
                    float vv = sacc[slot];
                    vv += __shfl_xor_sync(0xffffffffu, vv, 1);
                    vv += __shfl_xor_sync(0xffffffffu, vv, 2);
                    if (tg == 0) {
                        int mf = slot >> 1, h = slot & 1;
                        int lrow = mw * 64 + mf * 16 + h * 8 + qid;
                        s_red2[nw * 128 + lrow] = vv;
                    }
                    sacc[slot] = 0.0f;
                }
                __syncthreads();
                if (tid < 128) {
                    float t = 0.f;
#pragma unroll
                    for (int w = 0; w < 8; w++) t += s_red2[w * 128 + tid];
                    if (nt == 4) g_s_inst[(m0 + tid) * NCHUNK + chunk] = t;
                    else         g_s_reid[(m0 + tid) * NCHUNK + chunk] = t;
                }
            }
        }
    }

    __syncthreads();
    if (tid < 128)
        g_pcnt[(m0 + tid) * NCHUNK + chunk] = s_pcnt[tid];
}

// ---------------------------------------------------------------------------
// Finalize: 32 CTAs x 128 threads, one row per thread; last CTA sums all.
// ---------------------------------------------------------------------------
__global__ void __launch_bounds__(128)
finalize_kernel(const int* __restrict__ roi_label,
                const int* __restrict__ reid_labels, float* __restrict__ out)
{
    __shared__ float sred[4][5];
    __shared__ int s_last;
    int tid = threadIdx.x, wid = tid >> 5, lane = tid & 31;
    int m = blockIdx.x * 128 + tid;

    int t = roi_label[m] - 1;
    bool v = (t >= 0);
    int label = v ? t : 0;
    int lreid = reid_labels[label];
    bool v2 = v && (lreid >= 0);
    int lr = lreid > 0 ? lreid : 0;
    bool v3 = v2 && (lr != IGNORE_INDEX);

    float instS = 0.f, ceS = 0.f;
    if (v2) {
        float s = 0.f;
#pragma unroll
        for (int c = 0; c < NCHUNK; c++) s += g_s_inst[m * NCHUNK + c];
        float lse = (s > 0.f) ? (30.f + logf(s)) : -1e30f;
        int cnt = 0;
        float sum = 0.f;
#pragma unroll
        for (int c = 0; c < NCHUNK; c++) {
            int pc = g_pcnt[m * NCHUNK + c];
            cnt += pc;
            int pl = pc < CAPC ? pc : CAPC;
            for (int q = 0; q < pl; q++)
                sum += log1pf(expf(lse - g_posx[(m * NCHUNK + c) * CAPC + q]));
        }
        instS = sum / fmaxf((float)cnt, 1.f);
        if (v3) {
            float s2 = 0.f;
#pragma unroll
            for (int c = 0; c < NCHUNK; c++) s2 += g_s_reid[m * NCHUNK + c];
            ceS = (30.f + logf(s2)) - g_xt[m];
        }
    }
    float vals[5] = {instS, ceS, v ? 1.f : 0.f, v2 ? 1.f : 0.f, v3 ? 1.f : 0.f};
#pragma unroll
    for (int k = 0; k < 5; k++)
#pragma unroll
        for (int o = 16; o; o >>= 1)
            vals[k] += __shfl_xor_sync(0xffffffffu, vals[k], o);
    if (lane == 0)
        for (int k = 0; k < 5; k++) sred[wid][k] = vals[k];
    __syncthreads();
    if (tid == 0) {
        float tot[5] = {0, 0, 0, 0, 0};
        for (int w = 0; w < 4; w++)
            for (int k = 0; k < 5; k++) tot[k] += sred[w][k];
        for (int k = 0; k < 5; k++) g_part[blockIdx.x][k] = tot[k];
        __threadfence();
        int o = atomicAdd(&g_ticket, 1);
        s_last = (o == NMTILE - 1) ? 1 : 0;
    }
    __syncthreads();
    if (s_last) {
        // sum 1024 fc partials: each thread 8 entries in fixed order
        float fcS = 0.f;
#pragma unroll
        for (int q = 0; q < 8; q++) fcS += g_fc[tid * 8 + q];
#pragma unroll
        for (int o = 16; o; o >>= 1) fcS += __shfl_xor_sync(0xffffffffu, fcS, o);
        if (lane == 0) sred[wid][0] = fcS;
        __syncthreads();
        if (tid == 0) {
            float fc = sred[0][0] + sred[1][0] + sred[2][0] + sred[3][0];
            float tot[5] = {0, 0, 0, 0, 0};
            for (int b = 0; b < NMTILE; b++)
                for (int k = 0; k < 5; k++) tot[k] += g_part[b][k];
            out[0] = fc / (fmaxf(tot[2], 1.f) * (float)NF)
                   + tot[1] / fmaxf(tot[4], 1.f)
                   + tot[0] / fmaxf(tot[3], 1.f);
        }
    }
}

// ---------------------------------------------------------------------------
extern "C" void kernel_launch(void* const* d_in, const int* in_sizes, int n_in,
                              void* d_out, int out_size) {
    const float* inputs      = (const float*)d_in[0];
    const int*   roi_label   = (const int*)d_in[1];
    const float* lut_inst    = (const float*)d_in[2];
    const float* reid_lut    = (const float*)d_in[3];
    const int*   reid_labels = (const int*)d_in[4];
    float* out = (float*)d_out;

    cudaFuncSetAttribute(main_kernel, cudaFuncAttributeMaxDynamicSharedMemorySize,
                         SMEM_TOTAL);

    convert_kernel<<<CONV_GRID, 256>>>(inputs, lut_inst, reid_lut, roi_label);
    main_kernel<<<dim3(NMTILE, NCHUNK), 512, SMEM_TOTAL>>>(roi_label, reid_labels);
    finalize_kernel<<<NMTILE, 128>>>(roi_label, reid_labels, out);
}